// round 4
// baseline (speedup 1.0000x reference)
#include <cuda_runtime.h>

#define NSEG 2048
#define HBINS 65536
#define NMAX 4000000

#define ALPHA 0.1f
#define BETA  0.1f
#define CAPACITY 1000.0f

// ---------------- device scratch (static, allocation-free) ----------------
__device__ double g_sum_nllw;
__device__ double g_sum_w;
__device__ float g_cnt[NSEG];
__device__ float g_psum[NSEG];
__device__ float g_rate[NSEG];
__device__ float g_dws[NSEG];
__device__ unsigned int g_hist[HBINS];        // top-16-bit histogram of d_obs (valid only)
__device__ unsigned int g_hist2[2 * HBINS];   // refine histograms (lo bin, hi bin)
__device__ __align__(16) float g_dobs[NMAX];  // compacted d_obs (sentinel for invalid)
__device__ unsigned int g_sel[5];             // binLo, remLo, binHi, remHi, n_valid
__device__ float g_frac;

// ---------------- kernel 0: zero scratch (required every graph replay) ----
__global__ void zero_kernel() {
    int i = blockIdx.x * blockDim.x + threadIdx.x;
    if (i < 2 * HBINS) g_hist2[i] = 0u;
    if (i < HBINS) g_hist[i] = 0u;
    if (i < NSEG) {
        g_cnt[i] = 0.0f; g_psum[i] = 0.0f; g_rate[i] = 0.0f; g_dws[i] = 0.0f;
    }
    if (i == 0) { g_sum_nllw = 0.0; g_sum_w = 0.0; }
}

// ---------------- kernel 1: main streaming pass ---------------------------
__global__ void __launch_bounds__(256) pass1_kernel(
    const float2* __restrict__ logits,
    const int* __restrict__ y,
    const int* __restrict__ mask,        // bool stored as int32 (nonzero = true)
    const float* __restrict__ xraw,
    const int* __restrict__ widx,
    const float* __restrict__ cw,
    int n)
{
    __shared__ float s_cnt[NSEG];
    __shared__ float s_ps[NSEG];
    __shared__ float s_rt[NSEG];
    __shared__ float s_dw[NSEG];
    __shared__ float s_red[16];

    int tid = threadIdx.x;
    for (int i = tid; i < NSEG; i += blockDim.x) {
        s_cnt[i] = 0.0f; s_ps[i] = 0.0f; s_rt[i] = 0.0f; s_dw[i] = 0.0f;
    }
    __syncthreads();

    const float cw0 = __ldg(&cw[0]);
    const float cw1 = __ldg(&cw[1]);

    float acc_nllw = 0.0f, acc_w = 0.0f;

    int stride = gridDim.x * blockDim.x;
    for (int i = blockIdx.x * blockDim.x + tid; i < n; i += stride) {
        float2 lg = logits[i];
        int yi = y[i];
        int m = mask[i];
        int w = widx[i];
        // x_raw columns 2 (d_obs), 3 (rate): contiguous float2 at row*8+2
        float2 x23 = *reinterpret_cast<const float2*>(xraw + (size_t)i * 8 + 2);

        float mx = fmaxf(lg.x, lg.y);
        float e0 = __expf(lg.x - mx);
        float e1 = __expf(lg.y - mx);
        float se = e0 + e1;
        float lse = mx + __logf(se);
        float ly = yi ? lg.y : lg.x;
        float nll = lse - ly;
        float maskf = m ? 1.0f : 0.0f;
        float wyv = (yi ? cw1 : cw0) * maskf;
        acc_nllw += nll * wyv;
        acc_w += wyv;

        float p = e1 / se;  // softmax[:,1]
        bool valid = (m != 0) && (w >= 0);
        float dobs = fmaxf(x23.x, 0.0f);
        float rate = fmaxf(x23.y, 0.0f);

        unsigned int ub = __float_as_uint(dobs) >> 16;

        // warp-aggregated global histogram atomic (d_obs has ~50% exact
        // zeros -> bin(0.0) would otherwise serialize ~2M same-address
        // atomics; match_any aggregation cuts that by up to 32x)
        unsigned amask = __activemask();
        unsigned vm = __ballot_sync(amask, valid);
        if (valid) {
            unsigned peers = __match_any_sync(vm, ub);
            int leader = __ffs(peers) - 1;
            if ((tid & 31) == leader)
                atomicAdd(&g_hist[ub], (unsigned)__popc(peers));

            atomicAdd(&s_cnt[w], 1.0f);
            atomicAdd(&s_ps[w], p);
            atomicAdd(&s_rt[w], p * rate);
            atomicAdd(&s_dw[w], p * dobs);
            g_dobs[i] = dobs;
        } else {
            g_dobs[i] = __uint_as_float(0xFFFFFFFFu);  // sentinel
        }
    }

    // block reduce (2 floats)
    #pragma unroll
    for (int o = 16; o > 0; o >>= 1) {
        acc_nllw += __shfl_down_sync(0xFFFFFFFFu, acc_nllw, o);
        acc_w    += __shfl_down_sync(0xFFFFFFFFu, acc_w, o);
    }
    int warp = tid >> 5, lane = tid & 31;
    if (lane == 0) { s_red[warp] = acc_nllw; s_red[warp + 8] = acc_w; }
    __syncthreads();
    if (tid == 0) {
        float a = 0.0f, b = 0.0f;
        int nwarps = blockDim.x >> 5;
        for (int k = 0; k < nwarps; k++) { a += s_red[k]; b += s_red[k + 8]; }
        atomicAdd(&g_sum_nllw, (double)a);
        atomicAdd(&g_sum_w, (double)b);
    }
    __syncthreads();

    // flush segment bins
    for (int i = tid; i < NSEG; i += blockDim.x) {
        float c = s_cnt[i];
        if (c != 0.0f) {
            atomicAdd(&g_cnt[i], c);
            atomicAdd(&g_psum[i], s_ps[i]);
            atomicAdd(&g_rate[i], s_rt[i]);
            atomicAdd(&g_dws[i], s_dw[i]);
        }
    }
}

// ---------------- kernel 2: find top-16-bit bins for both ranks -----------
__global__ void select_kernel() {
    __shared__ unsigned int part[1024];
    int t = threadIdx.x;
    unsigned int base = (unsigned)t * 64;
    unsigned int s = 0;
    for (int j = 0; j < 64; j++) s += g_hist[base + j];
    part[t] = s;
    __syncthreads();
    for (int off = 1; off < 1024; off <<= 1) {
        unsigned int v = (t >= off) ? part[t - off] : 0u;
        __syncthreads();
        part[t] += v;
        __syncthreads();
    }
    unsigned int n = part[1023];
    unsigned int before = part[t] - s;

    float nf = (float)n;
    float pos = fmaxf(0.75f * (nf - 1.0f), 0.0f);
    float fl = floorf(pos);
    unsigned int rlo = (unsigned int)fl;
    unsigned int rhi = (unsigned int)ceilf(pos);
    if (t == 0) { g_frac = pos - fl; g_sel[4] = n; }

    unsigned int c = before;
    for (int j = 0; j < 64; j++) {
        unsigned int h = g_hist[base + j];
        if (h) {
            if (rlo >= c && rlo < c + h) { g_sel[0] = base + j; g_sel[1] = rlo - c; }
            if (rhi >= c && rhi < c + h) { g_sel[2] = base + j; g_sel[3] = rhi - c; }
        }
        c += h;
    }
}

// ---------------- kernel 3: refine histogram inside the selected bins -----
__global__ void __launch_bounds__(256) refine_kernel(int n) {
    unsigned int binLo = g_sel[0];
    unsigned int binHi = g_sel[2];
    int n4 = n >> 2;
    int stride = gridDim.x * blockDim.x;
    const uint4* d4 = reinterpret_cast<const uint4*>(g_dobs);
    for (int i = blockIdx.x * blockDim.x + threadIdx.x; i < n4; i += stride) {
        uint4 v = d4[i];
        unsigned int u, b;
        u = v.x; b = u >> 16;
        if (b == binLo) atomicAdd(&g_hist2[u & 0xFFFFu], 1u);
        else if (b == binHi) atomicAdd(&g_hist2[HBINS + (u & 0xFFFFu)], 1u);
        u = v.y; b = u >> 16;
        if (b == binLo) atomicAdd(&g_hist2[u & 0xFFFFu], 1u);
        else if (b == binHi) atomicAdd(&g_hist2[HBINS + (u & 0xFFFFu)], 1u);
        u = v.z; b = u >> 16;
        if (b == binLo) atomicAdd(&g_hist2[u & 0xFFFFu], 1u);
        else if (b == binHi) atomicAdd(&g_hist2[HBINS + (u & 0xFFFFu)], 1u);
        u = v.w; b = u >> 16;
        if (b == binLo) atomicAdd(&g_hist2[u & 0xFFFFu], 1u);
        else if (b == binHi) atomicAdd(&g_hist2[HBINS + (u & 0xFFFFu)], 1u);
    }
    // tail
    if (blockIdx.x == 0 && threadIdx.x < (n & 3)) {
        unsigned int u = __float_as_uint(g_dobs[(n4 << 2) + threadIdx.x]);
        unsigned int b = u >> 16;
        if (b == binLo) atomicAdd(&g_hist2[u & 0xFFFFu], 1u);
        else if (b == binHi) atomicAdd(&g_hist2[HBINS + (u & 0xFFFFu)], 1u);
    }
}

// helper: block-wide rank find over a 65536-bin histogram (1024 threads)
__device__ void find_rank(const unsigned int* hist, unsigned int rank,
                          unsigned int* s_part, unsigned int* s_result) {
    int t = threadIdx.x;
    unsigned int base = (unsigned)t * 64;
    unsigned int s = 0;
    for (int j = 0; j < 64; j++) s += hist[base + j];
    s_part[t] = s;
    __syncthreads();
    for (int off = 1; off < 1024; off <<= 1) {
        unsigned int v = (t >= off) ? s_part[t - off] : 0u;
        __syncthreads();
        s_part[t] += v;
        __syncthreads();
    }
    unsigned int c = s_part[t] - s;
    for (int j = 0; j < 64; j++) {
        unsigned int h = hist[base + j];
        if (h && rank >= c && rank < c + h) *s_result = base + j;
        c += h;
    }
    __syncthreads();
}

// ---------------- kernel 4: finalize quantile + segment epilogue ----------
__global__ void final_kernel(float* __restrict__ out) {
    __shared__ unsigned int part[1024];
    __shared__ unsigned int s_lo16, s_hi16;
    __shared__ float s_red[96];

    int t = threadIdx.x;
    unsigned int n = g_sel[4];
    unsigned int binLo = g_sel[0], binHi = g_sel[2];
    bool same = (binLo == binHi);

    if (t == 0) { s_lo16 = 0; s_hi16 = 0; }
    __syncthreads();

    find_rank(g_hist2, g_sel[1], part, &s_lo16);
    if (same) {
        find_rank(g_hist2, g_sel[3], part, &s_hi16);
    } else {
        find_rank(g_hist2 + HBINS, g_sel[3], part, &s_hi16);
    }

    float ref_dobs;
    if (n > 0) {
        float vlo = __uint_as_float((binLo << 16) | s_lo16);
        float vhi = __uint_as_float((binHi << 16) | s_hi16);
        float frac = g_frac;
        float q = vlo * (1.0f - frac) + vhi * frac;
        ref_dobs = fmaxf(q, 1e-6f);
    } else {
        ref_dobs = 1.0f;
    }
    float inv_ref = 1.0f / ref_dobs;

    // segment epilogue
    float nk = 0.0f, sf = 0.0f, sl = 0.0f;
    for (int w = t; w < NSEG; w += blockDim.x) {
        float cnt = g_cnt[w];
        float ps = g_psum[w];
        float rr = g_rate[w] / (CAPACITY + 1e-6f);
        float dm = g_dws[w] / (ps + 1e-6f);
        float bu = fmaxf(rr - 1.0f, 0.0f);
        float flow = bu * bu;
        float rho = fminf(fmaxf(rr, 0.0f), 0.99f);
        float dth = 1.0f / (1.0f - rho + 1e-6f);
        float lat = fmaxf(dth - dm * inv_ref, 0.0f);
        float keep = (cnt >= 2.0f && ps >= 1e-6f) ? 1.0f : 0.0f;
        nk += keep;
        sf += flow * keep;
        sl += lat * keep;
    }
    #pragma unroll
    for (int o = 16; o > 0; o >>= 1) {
        nk += __shfl_down_sync(0xFFFFFFFFu, nk, o);
        sf += __shfl_down_sync(0xFFFFFFFFu, sf, o);
        sl += __shfl_down_sync(0xFFFFFFFFu, sl, o);
    }
    int warp = t >> 5, lane = t & 31;
    if (lane == 0) { s_red[warp] = nk; s_red[32 + warp] = sf; s_red[64 + warp] = sl; }
    __syncthreads();
    if (t == 0) {
        float a = 0.0f, b = 0.0f, c = 0.0f;
        for (int k = 0; k < 32; k++) { a += s_red[k]; b += s_red[32 + k]; c += s_red[64 + k]; }
        float denom = fmaxf(a, 1.0f);
        float l_flow = (a > 0.0f) ? b / denom : 0.0f;
        float l_lat  = (a > 0.0f) ? c / denom : 0.0f;
        float l_data = (float)(g_sum_nllw / g_sum_w);
        out[0] = l_data + ALPHA * l_flow + BETA * l_lat;
        out[1] = l_data;
        out[2] = l_flow;
        out[3] = l_lat;
    }
}

// ---------------- launch ---------------------------------------------------
extern "C" void kernel_launch(void* const* d_in, const int* in_sizes, int n_in,
                              void* d_out, int out_size) {
    const float* logits = (const float*)d_in[0];
    const int* y = (const int*)d_in[1];
    const int* mask = (const int*)d_in[2];
    const float* xraw = (const float*)d_in[3];
    const int* widx = (const int*)d_in[4];
    const float* cw = (const float*)d_in[5];
    float* out = (float*)d_out;

    int n = in_sizes[1];  // y has N elements
    if (n > NMAX) n = NMAX;

    zero_kernel<<<512, 256>>>();
    pass1_kernel<<<592, 256>>>((const float2*)logits, y, mask, xraw, widx, cw, n);
    select_kernel<<<1, 1024>>>();
    refine_kernel<<<512, 256>>>(n);
    final_kernel<<<1, 1024>>>(out);
}

// round 5
// speedup vs baseline: 5.8392x; 5.8392x over previous
#include <cuda_runtime.h>

#define NSEG 2048
#define NB1 2048       // level-1: top 11 bits of float pattern
#define NB2 4096       // level-2: bits [20:9]
#define NB3 512        // level-3: bits [8:0]
#define CANDMAX 262144
#define STAGECAP 1024
#define NMAX 4000000

#define ALPHA 0.1f
#define BETA  0.1f
#define CAPACITY 1000.0f

// ---------------- device scratch ----------------
__device__ double g_sum_nllw;
__device__ double g_sum_w;
__device__ float g_cnt[NSEG];
__device__ float g_psum[NSEG];
__device__ float g_rate[NSEG];
__device__ float g_dws[NSEG];
__device__ unsigned g_h1[NB1];
__device__ unsigned g_h2a[NB2];
__device__ unsigned g_h2b[NB2];
__device__ unsigned g_h3a[NB3];
__device__ unsigned g_h3b[NB3];
__device__ unsigned g_candA[CANDMAX];
__device__ unsigned g_candB[CANDMAX];
__device__ unsigned g_ccA, g_ccB;
__device__ __align__(16) float g_dobs[NMAX];
__device__ unsigned g_selL1[4];   // {bin1Lo, remLo, bin1Hi, remHi}
__device__ unsigned g_selL2[4];   // {mid12Lo, remLo2, mid12Hi, remHi2}
__device__ float g_frac;
__device__ unsigned g_nvalid;

// ---------------- kernel: zero scratch ----------------
__global__ void zero_kernel() {
    int gt = blockIdx.x * blockDim.x + threadIdx.x;
    int gs = gridDim.x * blockDim.x;
    for (int i = gt; i < NB1; i += gs) g_h1[i] = 0u;
    for (int i = gt; i < NB2; i += gs) { g_h2a[i] = 0u; g_h2b[i] = 0u; }
    for (int i = gt; i < NB3; i += gs) { g_h3a[i] = 0u; g_h3b[i] = 0u; }
    for (int i = gt; i < NSEG; i += gs) {
        g_cnt[i] = 0.0f; g_psum[i] = 0.0f; g_rate[i] = 0.0f; g_dws[i] = 0.0f;
    }
    if (gt == 0) {
        g_sum_nllw = 0.0; g_sum_w = 0.0;
        g_ccA = 0u; g_ccB = 0u;
        g_selL1[0] = g_selL1[1] = g_selL1[2] = g_selL1[3] = 0u;
        g_selL2[0] = g_selL2[1] = g_selL2[2] = g_selL2[3] = 0u;
        g_frac = 0.0f; g_nvalid = 0u;
    }
}

__global__ void nop_kernel() {}

// ---------------- pass1: fused CE + segments + level-1 hist + dobs ----------
__global__ void __launch_bounds__(512) pass1_kernel(
    const float4* __restrict__ logits4,
    const int2* __restrict__ y2,
    const int2* __restrict__ m2,
    const float* __restrict__ xraw,
    const int2* __restrict__ w2,
    const float* __restrict__ cw,
    int n)
{
    __shared__ float s_cnt[NSEG];
    __shared__ float s_ps[NSEG];
    __shared__ float s_rt[NSEG];
    __shared__ float s_dw[NSEG];
    __shared__ unsigned s_h1[NB1];
    __shared__ float s_red[32];

    int tid = threadIdx.x;
    for (int i = tid; i < NSEG; i += blockDim.x) {
        s_cnt[i] = 0.0f; s_ps[i] = 0.0f; s_rt[i] = 0.0f; s_dw[i] = 0.0f;
        s_h1[i] = 0u;
    }
    __syncthreads();

    const float cw0 = __ldg(&cw[0]);
    const float cw1 = __ldg(&cw[1]);

    float acc_nllw = 0.0f, acc_w = 0.0f;

    int npair = n >> 1;
    int gstride = gridDim.x * blockDim.x;
    for (int j = blockIdx.x * blockDim.x + tid; j < npair; j += gstride) {
        float4 lg = logits4[j];
        int2 yy = y2[j];
        int2 mm = m2[j];
        int2 ww = w2[j];
        int i0 = j * 2;
        float2 xa = *reinterpret_cast<const float2*>(xraw + (size_t)i0 * 8 + 2);
        float2 xb = *reinterpret_cast<const float2*>(xraw + (size_t)(i0 + 1) * 8 + 2);

        // ---- row 0 ----
        {
            float l0 = lg.x, l1 = lg.y;
            float mx = fmaxf(l0, l1);
            float e0 = __expf(l0 - mx);
            float e1 = __expf(l1 - mx);
            float se = e0 + e1;
            float lse = mx + __logf(se);
            float nll = lse - (yy.x ? l1 : l0);
            float wyv = (yy.x ? cw1 : cw0) * (mm.x ? 1.0f : 0.0f);
            acc_nllw += nll * wyv;
            acc_w += wyv;
            float p = e1 / se;
            bool valid = (mm.x != 0) && (ww.x >= 0);
            float dobs = fmaxf(xa.x, 0.0f);
            float rate = fmaxf(xa.y, 0.0f);
            if (valid) {
                atomicAdd(&s_cnt[ww.x], 1.0f);
                atomicAdd(&s_ps[ww.x], p);
                atomicAdd(&s_rt[ww.x], p * rate);
                atomicAdd(&s_dw[ww.x], p * dobs);
                atomicAdd(&s_h1[__float_as_uint(dobs) >> 21], 1u);
                g_dobs[i0] = dobs;
            } else {
                g_dobs[i0] = __uint_as_float(0xFFFFFFFFu);
            }
        }
        // ---- row 1 ----
        {
            float l0 = lg.z, l1 = lg.w;
            float mx = fmaxf(l0, l1);
            float e0 = __expf(l0 - mx);
            float e1 = __expf(l1 - mx);
            float se = e0 + e1;
            float lse = mx + __logf(se);
            float nll = lse - (yy.y ? l1 : l0);
            float wyv = (yy.y ? cw1 : cw0) * (mm.y ? 1.0f : 0.0f);
            acc_nllw += nll * wyv;
            acc_w += wyv;
            float p = e1 / se;
            bool valid = (mm.y != 0) && (ww.y >= 0);
            float dobs = fmaxf(xb.x, 0.0f);
            float rate = fmaxf(xb.y, 0.0f);
            if (valid) {
                atomicAdd(&s_cnt[ww.y], 1.0f);
                atomicAdd(&s_ps[ww.y], p);
                atomicAdd(&s_rt[ww.y], p * rate);
                atomicAdd(&s_dw[ww.y], p * dobs);
                atomicAdd(&s_h1[__float_as_uint(dobs) >> 21], 1u);
                g_dobs[i0 + 1] = dobs;
            } else {
                g_dobs[i0 + 1] = __uint_as_float(0xFFFFFFFFu);
            }
        }
    }

    // odd tail row (n odd only)
    if ((n & 1) && blockIdx.x == 0 && tid == 0) {
        int i = n - 1;
        const float* lgs = reinterpret_cast<const float*>(logits4);
        float l0 = lgs[2 * i], l1 = lgs[2 * i + 1];
        int yi = reinterpret_cast<const int*>(y2)[i];
        int m = reinterpret_cast<const int*>(m2)[i];
        int w = reinterpret_cast<const int*>(w2)[i];
        float2 x23 = *reinterpret_cast<const float2*>(xraw + (size_t)i * 8 + 2);
        float mx = fmaxf(l0, l1);
        float e0 = __expf(l0 - mx);
        float e1 = __expf(l1 - mx);
        float se = e0 + e1;
        float lse = mx + __logf(se);
        float nll = lse - (yi ? l1 : l0);
        float wyv = (yi ? cw1 : cw0) * (m ? 1.0f : 0.0f);
        acc_nllw += nll * wyv;
        acc_w += wyv;
        float p = e1 / se;
        bool valid = (m != 0) && (w >= 0);
        float dobs = fmaxf(x23.x, 0.0f);
        float rate = fmaxf(x23.y, 0.0f);
        if (valid) {
            atomicAdd(&s_cnt[w], 1.0f);
            atomicAdd(&s_ps[w], p);
            atomicAdd(&s_rt[w], p * rate);
            atomicAdd(&s_dw[w], p * dobs);
            atomicAdd(&s_h1[__float_as_uint(dobs) >> 21], 1u);
            g_dobs[i] = dobs;
        } else {
            g_dobs[i] = __uint_as_float(0xFFFFFFFFu);
        }
    }

    // CE block reduce
    #pragma unroll
    for (int o = 16; o > 0; o >>= 1) {
        acc_nllw += __shfl_down_sync(0xFFFFFFFFu, acc_nllw, o);
        acc_w    += __shfl_down_sync(0xFFFFFFFFu, acc_w, o);
    }
    int warp = tid >> 5, lane = tid & 31;
    if (lane == 0) { s_red[warp] = acc_nllw; s_red[warp + 16] = acc_w; }
    __syncthreads();
    if (tid == 0) {
        float a = 0.0f, b = 0.0f;
        int nwarps = blockDim.x >> 5;
        for (int k = 0; k < nwarps; k++) { a += s_red[k]; b += s_red[k + 16]; }
        atomicAdd(&g_sum_nllw, (double)a);
        atomicAdd(&g_sum_w, (double)b);
    }

    // flush segment bins + level-1 histogram
    for (int i = tid; i < NSEG; i += blockDim.x) {
        float c = s_cnt[i];
        if (c != 0.0f) {
            atomicAdd(&g_cnt[i], c);
            atomicAdd(&g_psum[i], s_ps[i]);
            atomicAdd(&g_rate[i], s_rt[i]);
            atomicAdd(&g_dws[i], s_dw[i]);
        }
        unsigned h = s_h1[i];
        if (h) atomicAdd(&g_h1[i], h);
    }
}

// ---------------- sel1: pick level-1 bins for both ranks ----------------
__global__ void sel1_kernel() {
    __shared__ unsigned part[1024];
    int t = threadIdx.x;
    unsigned b0 = g_h1[2 * t], b1 = g_h1[2 * t + 1];
    unsigned s = b0 + b1;
    part[t] = s;
    __syncthreads();
    for (int off = 1; off < 1024; off <<= 1) {
        unsigned v = (t >= off) ? part[t - off] : 0u;
        __syncthreads();
        part[t] += v;
        __syncthreads();
    }
    unsigned n = part[1023];
    unsigned before = part[t] - s;

    float nf = (float)n;
    float pos = fmaxf(0.75f * (nf - 1.0f), 0.0f);
    float fl = floorf(pos);
    unsigned rlo = (unsigned)fl;
    unsigned rhi = (unsigned)ceilf(pos);
    if (t == 0) { g_frac = pos - fl; g_nvalid = n; }

    unsigned c = before;
    if (b0) {
        if (rlo >= c && rlo < c + b0) { g_selL1[0] = 2 * t;     g_selL1[1] = rlo - c; }
        if (rhi >= c && rhi < c + b0) { g_selL1[2] = 2 * t;     g_selL1[3] = rhi - c; }
    }
    c += b0;
    if (b1) {
        if (rlo >= c && rlo < c + b1) { g_selL1[0] = 2 * t + 1; g_selL1[1] = rlo - c; }
        if (rhi >= c && rhi < c + b1) { g_selL1[2] = 2 * t + 1; g_selL1[3] = rhi - c; }
    }
}

// ---------------- lvl2: mid-12-bit hist + candidate compaction -------------
__global__ void __launch_bounds__(384) lvl2_kernel(int n) {
    __shared__ unsigned sa[NB2];
    __shared__ unsigned sb[NB2];
    __shared__ unsigned stgA[STAGECAP];
    __shared__ unsigned stgB[STAGECAP];
    __shared__ unsigned scA, scB, baseA, baseB;

    int tid = threadIdx.x;
    for (int i = tid; i < NB2; i += blockDim.x) { sa[i] = 0u; sb[i] = 0u; }
    if (tid == 0) { scA = 0u; scB = 0u; }
    __syncthreads();

    unsigned pLo = g_selL1[0];
    unsigned pHi = g_selL1[2];

    int n4 = n >> 2;
    int gstride = gridDim.x * blockDim.x;
    const uint4* d4 = reinterpret_cast<const uint4*>(g_dobs);
    for (int i = blockIdx.x * blockDim.x + tid; i < n4; i += gstride) {
        uint4 v = d4[i];
        #pragma unroll
        for (int k = 0; k < 4; k++) {
            unsigned u = (k == 0) ? v.x : (k == 1) ? v.y : (k == 2) ? v.z : v.w;
            unsigned b = u >> 21;
            if (b == pLo) {
                atomicAdd(&sa[(u >> 9) & 0xFFFu], 1u);
                unsigned p = atomicAdd(&scA, 1u);
                if (p < STAGECAP) stgA[p] = u;
            }
            if (b == pHi) {
                atomicAdd(&sb[(u >> 9) & 0xFFFu], 1u);
                unsigned p = atomicAdd(&scB, 1u);
                if (p < STAGECAP) stgB[p] = u;
            }
        }
    }
    // scalar tail
    if (blockIdx.x == 0 && tid < (n & 3)) {
        unsigned u = __float_as_uint(g_dobs[(n4 << 2) + tid]);
        unsigned b = u >> 21;
        if (b == pLo) {
            atomicAdd(&sa[(u >> 9) & 0xFFFu], 1u);
            unsigned p = atomicAdd(&scA, 1u);
            if (p < STAGECAP) stgA[p] = u;
        }
        if (b == pHi) {
            atomicAdd(&sb[(u >> 9) & 0xFFFu], 1u);
            unsigned p = atomicAdd(&scB, 1u);
            if (p < STAGECAP) stgB[p] = u;
        }
    }
    __syncthreads();

    // flush sparse hists
    for (int i = tid; i < NB2; i += blockDim.x) {
        if (sa[i]) atomicAdd(&g_h2a[i], sa[i]);
        if (sb[i]) atomicAdd(&g_h2b[i], sb[i]);
    }
    unsigned nA = min(scA, (unsigned)STAGECAP);
    unsigned nB = min(scB, (unsigned)STAGECAP);
    if (tid == 0) {
        baseA = atomicAdd(&g_ccA, nA);
        baseB = atomicAdd(&g_ccB, nB);
    }
    __syncthreads();
    for (unsigned i = tid; i < nA; i += blockDim.x) {
        unsigned p = baseA + i;
        if (p < CANDMAX) g_candA[p] = stgA[i];
    }
    for (unsigned i = tid; i < nB; i += blockDim.x) {
        unsigned p = baseB + i;
        if (p < CANDMAX) g_candB[p] = stgB[i];
    }
}

// ---------------- sel2: pick mid-12 bins ----------------
__device__ void find_l2(const unsigned* hist, unsigned rank, unsigned* s_part,
                        unsigned out_idx) {
    int t = threadIdx.x;
    unsigned base = (unsigned)t * 4;
    unsigned h[4];
    unsigned s = 0;
    #pragma unroll
    for (int j = 0; j < 4; j++) { h[j] = hist[base + j]; s += h[j]; }
    s_part[t] = s;
    __syncthreads();
    for (int off = 1; off < 1024; off <<= 1) {
        unsigned v = (t >= off) ? s_part[t - off] : 0u;
        __syncthreads();
        s_part[t] += v;
        __syncthreads();
    }
    unsigned c = s_part[t] - s;
    #pragma unroll
    for (int j = 0; j < 4; j++) {
        if (h[j] && rank >= c && rank < c + h[j]) {
            g_selL2[out_idx] = base + j;
            g_selL2[out_idx + 1] = rank - c;
        }
        c += h[j];
    }
    __syncthreads();
}

__global__ void sel2_kernel() {
    __shared__ unsigned part[1024];
    find_l2(g_h2a, g_selL1[1], part, 0);
    find_l2(g_h2b, g_selL1[3], part, 2);
}

// ---------------- lvl3: low-9-bit hist from candidate lists ----------------
__global__ void lvl3_kernel() {
    unsigned mLo = g_selL2[0];
    unsigned mHi = g_selL2[2];
    unsigned cA = min(g_ccA, (unsigned)CANDMAX);
    unsigned cB = min(g_ccB, (unsigned)CANDMAX);
    unsigned cm = max(cA, cB);
    unsigned gstride = gridDim.x * blockDim.x;
    for (unsigned i = blockIdx.x * blockDim.x + threadIdx.x; i < cm; i += gstride) {
        if (i < cA) {
            unsigned u = g_candA[i];
            if (((u >> 9) & 0xFFFu) == mLo) atomicAdd(&g_h3a[u & 0x1FFu], 1u);
        }
        if (i < cB) {
            unsigned u = g_candB[i];
            if (((u >> 9) & 0xFFFu) == mHi) atomicAdd(&g_h3b[u & 0x1FFu], 1u);
        }
    }
}

// ---------------- final: reconstruct quantile + epilogue ----------------
__device__ unsigned find_l3(const unsigned* hist, unsigned rank,
                            unsigned* s_part, unsigned* s_result) {
    int t = threadIdx.x;
    unsigned h = (t < NB3) ? hist[t] : 0u;
    s_part[t] = h;
    __syncthreads();
    for (int off = 1; off < 1024; off <<= 1) {
        unsigned v = (t >= off) ? s_part[t - off] : 0u;
        __syncthreads();
        s_part[t] += v;
        __syncthreads();
    }
    unsigned c = s_part[t] - h;
    if (t < NB3 && h && rank >= c && rank < c + h) *s_result = (unsigned)t;
    __syncthreads();
    return *s_result;
}

__global__ void final_kernel(float* __restrict__ out) {
    __shared__ unsigned part[1024];
    __shared__ unsigned s_lo, s_hi;
    __shared__ float s_red[96];

    int t = threadIdx.x;
    if (t == 0) { s_lo = 0u; s_hi = 0u; }
    __syncthreads();

    unsigned lo9 = find_l3(g_h3a, g_selL2[1], part, &s_lo);
    unsigned hi9 = find_l3(g_h3b, g_selL2[3], part, &s_hi);

    unsigned n = g_nvalid;
    float ref_dobs;
    if (n > 0) {
        unsigned uLo = (g_selL1[0] << 21) | (g_selL2[0] << 9) | lo9;
        unsigned uHi = (g_selL1[2] << 21) | (g_selL2[2] << 9) | hi9;
        float vlo = __uint_as_float(uLo);
        float vhi = __uint_as_float(uHi);
        float frac = g_frac;
        float q = vlo * (1.0f - frac) + vhi * frac;
        ref_dobs = fmaxf(q, 1e-6f);
    } else {
        ref_dobs = 1.0f;
    }
    float inv_ref = 1.0f / ref_dobs;

    float nk = 0.0f, sf = 0.0f, sl = 0.0f;
    for (int w = t; w < NSEG; w += blockDim.x) {
        float cnt = g_cnt[w];
        float ps = g_psum[w];
        float rr = g_rate[w] / (CAPACITY + 1e-6f);
        float dm = g_dws[w] / (ps + 1e-6f);
        float bu = fmaxf(rr - 1.0f, 0.0f);
        float flow = bu * bu;
        float rho = fminf(fmaxf(rr, 0.0f), 0.99f);
        float dth = 1.0f / (1.0f - rho + 1e-6f);
        float lat = fmaxf(dth - dm * inv_ref, 0.0f);
        float keep = (cnt >= 2.0f && ps >= 1e-6f) ? 1.0f : 0.0f;
        nk += keep;
        sf += flow * keep;
        sl += lat * keep;
    }
    #pragma unroll
    for (int o = 16; o > 0; o >>= 1) {
        nk += __shfl_down_sync(0xFFFFFFFFu, nk, o);
        sf += __shfl_down_sync(0xFFFFFFFFu, sf, o);
        sl += __shfl_down_sync(0xFFFFFFFFu, sl, o);
    }
    int warp = t >> 5, lane = t & 31;
    if (lane == 0) { s_red[warp] = nk; s_red[32 + warp] = sf; s_red[64 + warp] = sl; }
    __syncthreads();
    if (t == 0) {
        float a = 0.0f, b = 0.0f, c = 0.0f;
        for (int k = 0; k < 32; k++) { a += s_red[k]; b += s_red[32 + k]; c += s_red[64 + k]; }
        float denom = fmaxf(a, 1.0f);
        float l_flow = (a > 0.0f) ? b / denom : 0.0f;
        float l_lat  = (a > 0.0f) ? c / denom : 0.0f;
        float l_data = (float)(g_sum_nllw / g_sum_w);
        out[0] = l_data + ALPHA * l_flow + BETA * l_lat;
        out[1] = l_data;
        out[2] = l_flow;
        out[3] = l_lat;
    }
}

// ---------------- launch ----------------
extern "C" void kernel_launch(void* const* d_in, const int* in_sizes, int n_in,
                              void* d_out, int out_size) {
    const float* logits = (const float*)d_in[0];
    const int* y = (const int*)d_in[1];
    const int* mask = (const int*)d_in[2];
    const float* xraw = (const float*)d_in[3];
    const int* widx = (const int*)d_in[4];
    const float* cw = (const float*)d_in[5];
    float* out = (float*)d_out;

    int n = in_sizes[1];
    if (n > NMAX) n = NMAX;

    zero_kernel<<<32, 256>>>();
    nop_kernel<<<1, 32>>>();
    nop_kernel<<<1, 32>>>();
    pass1_kernel<<<592, 512>>>((const float4*)logits, (const int2*)y,
                               (const int2*)mask, xraw, (const int2*)widx, cw, n);
    sel1_kernel<<<1, 1024>>>();
    lvl2_kernel<<<740, 384>>>(n);
    sel2_kernel<<<1, 1024>>>();
    lvl3_kernel<<<64, 256>>>();
    final_kernel<<<1, 1024>>>(out);
}